// round 11
// baseline (speedup 1.0000x reference)
#include <cuda_runtime.h>
#include <math.h>

#define NEDGE 65536
#define NATOMS 2048
#define NK 69
#define NFEAT 216
#define EMBD 16
#define NELEM 94
#define H1D 256
#define H2D 128
#define EC 32        // edges per chunk in fused kernel
#define MAXCHUNK 256

// ---------------- scratch (device globals; no allocs allowed) ----------------
__device__ float g_feat[(size_t)NATOMS * NFEAT];      // [nat][216]
__device__ float g_embS[(size_t)NELEM * EMBD];        // [94][16]
__device__ float g_weff[(size_t)NELEM * NFEAT * H1D]; // [94][216][256] 20.8MB
__device__ float g_h1  [(size_t)NATOMS * H1D];
__device__ float g_h2  [(size_t)NATOMS * H2D];
__device__ int   g_alist[NATOMS];
__device__ int   g_seg[NATOMS + 1];
__device__ int   g_ck_lo[MAXCHUNK];
__device__ int   g_ck_hi[MAXCHUNK];
__device__ int   g_ck_s [MAXCHUNK];
__device__ int   g_nchunk;
__device__ double g_part[8];

// ---------------- angular tables (lx,ly,lz, fnorm, lambda) -------------------
// zeta=1: k 0..3, zeta=2: 4..13, zeta=3: 14..33, zeta=4: 34..68
__constant__ int c_lx[NK] = {
 0,0,0,1,
 0,0,0,1,0,0,0,1,1,2,
 0,0,0,1,0,0,0,1,1,2,0,0,0,0,1,1,1,2,2,3,
 0,0,0,1,0,0,0,1,1,2,0,0,0,0,1,1,1,2,2,3,0,0,0,0,0,1,1,1,1,2,2,2,3,3,4};
__constant__ int c_ly[NK] = {
 0,0,1,0,
 0,0,1,0,0,1,2,0,1,0,
 0,0,1,0,0,1,2,0,1,0,0,1,2,3,0,1,2,0,1,0,
 0,0,1,0,0,1,2,0,1,0,0,1,2,3,0,1,2,0,1,0,0,1,2,3,4,0,1,2,3,0,1,2,0,1,0};
__constant__ int c_lz[NK] = {
 0,1,0,0,
 0,1,0,0,2,1,0,1,0,0,
 0,1,0,0,2,1,0,1,0,0,3,2,1,0,2,1,0,1,0,0,
 0,1,0,0,2,1,0,1,0,0,3,2,1,0,2,1,0,1,0,0,4,3,2,1,0,3,2,1,0,2,1,0,1,0,0};
__constant__ float c_fn[NK] = {
 1,1,1,1,
 1,2,2,2,1,2,1,2,2,1,
 1,3,3,3,3,6,3,6,6,3,1,3,3,1,3,6,3,3,3,1,
 1,4,4,4,6,12,6,12,12,6,4,12,12,4,12,24,12,12,12,4,1,4,6,4,1,4,12,12,4,6,12,6,4,4,1};
__constant__ float c_lam[NK] = {
 1,-1,-1,-1,
 1,-1,-1,-1,1,1,1,1,1,1,
 1,-1,-1,-1,1,1,1,1,1,1,-1,-1,-1,-1,-1,-1,-1,-1,-1,-1,
 1,-1,-1,-1,1,1,1,1,1,1,-1,-1,-1,-1,-1,-1,-1,-1,-1,-1,1,1,1,1,1,1,1,1,1,1,1,1,1,1,1};

__device__ __forceinline__ float silu(float x) {
    // x * sigmoid(x) via fast exp + fast reciprocal (err ~1e-6, budget 1e-3)
    return x * __frcp_rn(1.0f + __expf(-x));
}

// ---------------- fused kernel shared-memory layout (float offsets) ----------
#define OFF_W1T 0        // [64][24] transposed Wr1          1536
#define OFF_B1  1536     // [64]                               64
#define OFF_W2  1600     // [64][120] Wr2 natural            7680
#define OFF_B2  9280     // [120]                             120
#define OFF_BAS 9400     // [EC][25]  basis (padded)          800
#define OFF_H   10200    // [EC][65]  hidden (padded)        2080
#define OFF_RAD 12280    // [EC][121] radial out (padded)    3872
#define OFF_GIJ 16152    // [EC][69]  angular combos         2208
// GI/F0 are only used AFTER the chunk loop -> alias the BAS/H/RAD region
#define OFF_GI  9400     // [2][69][24] accumulated gi       3312 (aliases)
#define OFF_F0  12712    // [2][24]   2-body partials          48 (aliases)
#define SMEM_FLOATS 18360
#define FUSED_SMEM_BYTES (SMEM_FLOATS * 4)   // 73440 B

// ============================================================================
// seg_kernel: g_seg[a] = first edge index with fa[e] >= a (fa is sorted)
// ============================================================================
__global__ __launch_bounds__(256) void seg_kernel(const int* __restrict__ fa)
{
    int e = blockIdx.x * 256 + threadIdx.x;
    if (e >= NEDGE) return;
    int cur = fa[e];
    int prev = (e == 0) ? -1 : fa[e - 1];
    for (int a = prev + 1; a <= cur; a++) g_seg[a] = e;
    if (e == NEDGE - 1)
        for (int a = cur + 1; a <= NATOMS; a++) g_seg[a] = NEDGE;
}

// ============================================================================
// Fused kernel: one block (256 threads) per atom; 3 blocks/SM enforced.
// Per chunk of up to 32 edges: P0 geometry (8 threads/edge), P1 layer1,
// P2 layer2 (16-wide j tiles, low register pressure), P3 gi accumulation.
// ============================================================================
__global__ __launch_bounds__(256, 3) void fused_kernel(
    const float* __restrict__ rij,
    const float* __restrict__ Wr1, const float* __restrict__ br1,
    const float* __restrict__ Wr2, const float* __restrict__ br2)
{
    extern __shared__ float sm[];
    int a = blockIdx.x;
    int t = threadIdx.x;

    // cooperative weight staging
    for (int idx = t; idx < 1536; idx += 256) {
        int j = idx / 24, i = idx % 24;
        sm[OFF_W1T + idx] = Wr1[i * 64 + j];      // transpose to [j][i]
    }
    for (int idx = t; idx < 64; idx += 256)   sm[OFF_B1 + idx] = br1[idx];
    for (int idx = t; idx < 7680; idx += 256) sm[OFF_W2 + idx] = Wr2[idx];
    for (int idx = t; idx < 120; idx += 256)  sm[OFF_B2 + idx] = br2[idx];

    int lo = g_seg[a], hi = g_seg[a + 1];   // precomputed segment bounds

    int e = t & 31, q = t >> 5;           // P0/P1/P2 roles
    // P3 roles: t<138 -> combo k=t>>1, parity p=t&1; t in [138,186) -> 2-body
    int k3 = t >> 1;
    int p3 = t & 1;
    int c3 = (k3 < 4) ? 1 : (k3 < 14) ? 2 : (k3 < 34) ? 3 : 4;
    float acc[24];
    #pragma unroll
    for (int r = 0; r < 24; r++) acc[r] = 0.f;
    float acc0 = 0.f;
    int r0 = (t - 138) >> 1, p0 = (t - 138) & 1;

    for (int base = lo; base < hi; base += EC) {
        int cnt = min(EC, hi - base);
        __syncthreads();   // protect smem reuse (prev P3 reads / weight staging)

        // ---- P0: per-edge geometry, 8 threads per edge (e, q):
        //      q handles basis i = q*3..q*3+2 and combos k = q*9..q*9+8
        if (e < cnt) {
            int ed = base + e;
            float x = rij[ed * 3 + 0], y = rij[ed * 3 + 1], z = rij[ed * 3 + 2];
            float r = sqrtf(x * x + y * y + z * z);
            float inv = 1.0f / r;
            float ux = x * inv, uy = y * inv, uz = z * inv;
            float rc = fminf(r, 6.0f);
            float fc = 0.5f * (cosf(3.14159265358979f * rc * (1.0f / 6.0f)) + 1.0f);
            #pragma unroll
            for (int uu = 0; uu < 3; uu++) {
                int i = q * 3 + uu;
                float d = r - (6.0f * (float)i / 23.0f);
                sm[OFF_BAS + e * 25 + i] = __expf(-8.0f * d * d) * fc;
            }
            float bx = ux + 1e-12f, by = uy + 1e-12f, bz = uz + 1e-12f;
            #pragma unroll
            for (int uu = 0; uu < 9; uu++) {
                int k = q * 9 + uu;
                if (k < NK) {
                    // trip counts are warp-uniform (k uniform within warp)
                    float v = c_fn[k];
                    int lx = c_lx[k], ly = c_ly[k], lz = c_lz[k];
                    for (int l = 0; l < lx; l++) v *= bx;
                    for (int l = 0; l < ly; l++) v *= by;
                    for (int l = 0; l < lz; l++) v *= bz;
                    sm[OFF_GIJ + e * 69 + k] = v;
                }
            }
        }
        __syncthreads();

        // ---- P1: layer1 h = silu(basis @ W1 + b1); thread (e, q) does 8 j's
        if (e < cnt) {
            float bas[24];
            #pragma unroll
            for (int i = 0; i < 24; i++) bas[i] = sm[OFF_BAS + e * 25 + i];
            #pragma unroll
            for (int jj = 0; jj < 8; jj++) {
                int j = q * 8 + jj;
                float s = sm[OFF_B1 + j];
                #pragma unroll
                for (int i0 = 0; i0 < 24; i0 += 4) {
                    float4 w = *(const float4*)&sm[OFF_W1T + j * 24 + i0];
                    s = fmaf(bas[i0 + 0], w.x, s);
                    s = fmaf(bas[i0 + 1], w.y, s);
                    s = fmaf(bas[i0 + 2], w.z, s);
                    s = fmaf(bas[i0 + 3], w.w, s);
                }
                sm[OFF_H + e * 65 + j] = silu(s);
            }
        }
        __syncthreads();

        // ---- P2: layer2 rad = silu(h @ W2 + b2).
        // Thread (e, q) owns output groups ib..ib+ng-1 (ng<=4); j processed
        // in 16-wide tiles so only hreg16[16] + acc4[16] live (low regs).
        if (e < cnt) {
            int ib = q * 4;
            int ng = min(4, 30 - ib);   // q=7 -> 2 groups
            float acc4[16];
            #pragma unroll
            for (int g = 0; g < 4; g++)
                #pragma unroll
                for (int u = 0; u < 4; u++)
                    acc4[g * 4 + u] = (g < ng) ? sm[OFF_B2 + (ib + g) * 4 + u] : 0.f;
            #pragma unroll
            for (int jt = 0; jt < 64; jt += 16) {
                float hreg16[16];
                #pragma unroll
                for (int jj = 0; jj < 16; jj++)
                    hreg16[jj] = sm[OFF_H + e * 65 + jt + jj];
                #pragma unroll
                for (int g = 0; g < 4; g++) {
                    if (g < ng) {
                        int o0 = (ib + g) * 4;
                        #pragma unroll
                        for (int jj = 0; jj < 16; jj++) {
                            float4 w = *(const float4*)&sm[OFF_W2 + (jt + jj) * 120 + o0];
                            float hv = hreg16[jj];
                            acc4[g * 4 + 0] = fmaf(hv, w.x, acc4[g * 4 + 0]);
                            acc4[g * 4 + 1] = fmaf(hv, w.y, acc4[g * 4 + 1]);
                            acc4[g * 4 + 2] = fmaf(hv, w.z, acc4[g * 4 + 2]);
                            acc4[g * 4 + 3] = fmaf(hv, w.w, acc4[g * 4 + 3]);
                        }
                    }
                }
            }
            #pragma unroll
            for (int g = 0; g < 4; g++) {
                if (g < ng) {
                    int o0 = (ib + g) * 4;
                    sm[OFF_RAD + e * 121 + o0 + 0] = silu(acc4[g * 4 + 0]);
                    sm[OFF_RAD + e * 121 + o0 + 1] = silu(acc4[g * 4 + 1]);
                    sm[OFF_RAD + e * 121 + o0 + 2] = silu(acc4[g * 4 + 2]);
                    sm[OFF_RAD + e * 121 + o0 + 3] = silu(acc4[g * 4 + 3]);
                }
            }
        }
        __syncthreads();

        // ---- P3: accumulate gi[k][r] (2 threads/combo over edge parity) and
        //          the 2-body term (2 threads/radial channel)
        if (t < 2 * NK) {
            for (int i = p3; i < cnt; i += 2) {
                float g = sm[OFF_GIJ + i * 69 + k3];
                #pragma unroll
                for (int r = 0; r < 24; r++)
                    acc[r] = fmaf(sm[OFF_RAD + i * 121 + r * 5 + c3], g, acc[r]);
            }
        } else if (t < 2 * NK + 48) {
            for (int i = p0; i < cnt; i += 2) acc0 += sm[OFF_RAD + i * 121 + r0 * 5];
        }
    }
    __syncthreads();   // after this, BAS/H/RAD region is dead -> GI/F0 alias it
    if (t < 2 * NK) {
        #pragma unroll
        for (int r = 0; r < 24; r++) sm[OFF_GI + (p3 * NK + k3) * 24 + r] = acc[r];
    } else if (t < 2 * NK + 48) {
        sm[OFF_F0 + p0 * 24 + r0] = acc0;
    }
    __syncthreads();

    // ---- features: [0:24]=2-body; then per zeta: lam+ (24), lam- (24)
    float* fo = g_feat + (size_t)a * NFEAT;
    for (int f = t; f < NFEAT; f += 256) {
        float v;
        if (f < 24) {
            v = sm[OFF_F0 + f] + sm[OFF_F0 + 24 + f];
        } else {
            int b   = f - 24;
            int blk = b / 24;       // 0..7
            int r   = b % 24;
            int zi  = blk >> 1;     // zeta index 0..3
            int sgn = blk & 1;      // 0: lambda=+1, 1: lambda=-1
            int ks = (zi == 0) ? 0 : (zi == 1) ? 4 : (zi == 2) ? 14 : 34;
            int ke = (zi == 0) ? 4 : (zi == 1) ? 14 : (zi == 2) ? 34 : 69;
            float s = 0.f;
            for (int k = ks; k < ke; k++) {
                float gv = sm[OFF_GI + k * 24 + r] + sm[OFF_GI + (NK + k) * 24 + r];
                float g2 = gv * gv;
                s += sgn ? g2 * c_lam[k] : g2;
            }
            v = s * (1.0f / (float)(1 << zi));   // 2^(1-z), z = zi+1
        }
        fo[f] = v;
    }
}

// ============================================================================
// per-species embedding embS[94][16] + counting sort + 32-atom chunk list
// ============================================================================
__global__ __launch_bounds__(256) void embsort_kernel(
    const float* __restrict__ Ws1, const float* __restrict__ bs1,
    const float* __restrict__ Ws2, const float* __restrict__ bs2,
    const int* __restrict__ species)
{
    __shared__ int cnt[NELEM];
    __shared__ int cur[NELEM];
    __shared__ int start[NELEM + 1];
    int t = threadIdx.x;

    if (t < NELEM) {
        int s = t;
        float hv[32];
        #pragma unroll
        for (int j = 0; j < 32; j++) hv[j] = silu(Ws1[s * 32 + j] + bs1[j]);
        #pragma unroll
        for (int m = 0; m < EMBD; m++) {
            float acc = bs2[m];
            #pragma unroll
            for (int j = 0; j < 32; j++) acc = fmaf(hv[j], Ws2[j * EMBD + m], acc);
            g_embS[s * EMBD + m] = acc;
        }
    }

    for (int i = t; i < NELEM; i += 256) cnt[i] = 0;
    __syncthreads();
    for (int a = t; a < NATOMS; a += 256) atomicAdd(&cnt[species[a]], 1);
    __syncthreads();
    if (t == 0) {
        int run = 0;
        for (int s = 0; s < NELEM; s++) {
            start[s] = run;
            cur[s] = run;
            run += cnt[s];
        }
        start[NELEM] = run;
        // build chunk list: per-species chunks of <=32 atoms
        int nc = 0;
        for (int s = 0; s < NELEM; s++) {
            for (int c0 = start[s]; c0 < start[s + 1]; c0 += 32) {
                g_ck_lo[nc] = c0;
                g_ck_hi[nc] = min(c0 + 32, start[s + 1]);
                g_ck_s[nc]  = s;
                nc++;
            }
        }
        g_nchunk = nc;
    }
    __syncthreads();
    for (int a = t; a < NATOMS; a += 256) {
        int s = species[a];
        int pos = atomicAdd(&cur[s], 1);
        g_alist[pos] = a;
    }
}

// ============================================================================
// W_eff[s][f][n] = sum_m embS[s][m] * Wa1[(f*16+m)*256 + n]
// grid = (216, 4): blockIdx.x = f, blockIdx.y selects 24-species slab
// ============================================================================
__global__ __launch_bounds__(256) void weff_kernel(const float* __restrict__ Wa1)
{
    __shared__ float Wsm[EMBD][H1D];    // 16KB
    __shared__ float Esm[24 * EMBD];    // 1.5KB
    int f = blockIdx.x;
    int s0 = blockIdx.y * 24;
    int s1 = min(s0 + 24, NELEM);
    int nsp = s1 - s0;
    int n = threadIdx.x;
    for (int idx = n; idx < EMBD * H1D; idx += 256) {
        int m = idx / H1D, nn = idx % H1D;
        Wsm[m][nn] = Wa1[(size_t)(f * EMBD + m) * H1D + nn];
    }
    for (int idx = n; idx < nsp * EMBD; idx += 256)
        Esm[idx] = g_embS[s0 * EMBD + idx];
    __syncthreads();
    for (int si = 0; si < nsp; si++) {
        float acc = 0.f;
        #pragma unroll
        for (int m = 0; m < EMBD; m++) acc = fmaf(Esm[si * EMBD + m], Wsm[m][n], acc);
        g_weff[((size_t)(s0 + si) * NFEAT + f) * H1D + n] = acc;
    }
}

// ============================================================================
// grouped GEMM: h1[a,n] = silu(sum_f feat[a,f]*W_eff[s,f,n] + ba1[n])
// grid = (MAXCHUNK, 2): blockIdx.x = chunk (<=32 atoms, single species),
// blockIdx.y = 128-wide n-half. 256 threads: nn = y*128 + (t&127); the 32
// atoms split 16+16 by t>>7. One chunk per block, 16-deep register blocking.
// ============================================================================
__global__ __launch_bounds__(256) void gemm1_kernel(const float* __restrict__ ba1)
{
    __shared__ float sf[32][NFEAT];   // 27.6KB
    __shared__ int   satom[32];
    int ck = blockIdx.x;
    if (ck >= g_nchunk) return;
    int t = threadIdx.x;
    int lo = g_ck_lo[ck], hi = g_ck_hi[ck], s = g_ck_s[ck];
    int cnt = hi - lo;
    int nn = blockIdx.y * 128 + (t & 127);
    int m0 = (t >> 7) * 16;

    if (t < 32) satom[t] = (t < cnt) ? g_alist[lo + t] : -1;
    __syncthreads();
    for (int idx = t; idx < 32 * NFEAT; idx += 256) {
        int m = idx / NFEAT, f = idx % NFEAT;
        int a = satom[m];
        sf[m][f] = (a >= 0) ? g_feat[(size_t)a * NFEAT + f] : 0.f;
    }
    __syncthreads();

    float bias = ba1[nn];
    const float* W = g_weff + (size_t)s * NFEAT * H1D + nn;

    float acc[16];
    #pragma unroll
    for (int m = 0; m < 16; m++) acc[m] = 0.f;
    for (int f = 0; f < NFEAT; f += 4) {
        float w0 = W[(size_t)(f + 0) * H1D];
        float w1 = W[(size_t)(f + 1) * H1D];
        float w2 = W[(size_t)(f + 2) * H1D];
        float w3 = W[(size_t)(f + 3) * H1D];
        #pragma unroll
        for (int m = 0; m < 16; m++) {
            float4 fv = *(const float4*)&sf[m0 + m][f];
            acc[m] = fmaf(fv.x, w0, acc[m]);
            acc[m] = fmaf(fv.y, w1, acc[m]);
            acc[m] = fmaf(fv.z, w2, acc[m]);
            acc[m] = fmaf(fv.w, w3, acc[m]);
        }
    }
    #pragma unroll
    for (int m = 0; m < 16; m++) {
        int a = satom[m0 + m];
        if (a >= 0) g_h1[(size_t)a * H1D + nn] = silu(acc[m] + bias);
    }
}

// ============================================================================
// GEMM2, 32x32 tiles: h2 = silu(h1 @ Wa2 + ba2); grid (4, 64), 256 threads
// ============================================================================
__global__ __launch_bounds__(256) void gemm2_kernel(
    const float* __restrict__ A, const float* __restrict__ B,
    const float* __restrict__ bias, float* __restrict__ C)
{
    const int N = H2D, K = H1D;
    __shared__ float As[32][33];
    __shared__ float Bs[32][33];
    int tid = threadIdx.x;
    int bm = blockIdx.y * 32, bn = blockIdx.x * 32;
    int lrow = tid / 8;            // 0..31
    int lcol = (tid % 8) * 4;      // 0,4,...,28
    int ty = tid / 16, tx = tid % 16;

    float acc[2][2] = {};
    for (int k0 = 0; k0 < K; k0 += 32) {
        float4 av = *(const float4*)(A + (size_t)(bm + lrow) * K + k0 + lcol);
        As[lcol + 0][lrow] = av.x;
        As[lcol + 1][lrow] = av.y;
        As[lcol + 2][lrow] = av.z;
        As[lcol + 3][lrow] = av.w;
        float4 bv = *(const float4*)(B + (size_t)(k0 + lrow) * N + bn + lcol);
        Bs[lrow][lcol + 0] = bv.x;
        Bs[lrow][lcol + 1] = bv.y;
        Bs[lrow][lcol + 2] = bv.z;
        Bs[lrow][lcol + 3] = bv.w;
        __syncthreads();
        #pragma unroll
        for (int kk = 0; kk < 32; kk++) {
            float a0 = As[kk][ty * 2 + 0];
            float a1 = As[kk][ty * 2 + 1];
            float b0 = Bs[kk][tx * 2 + 0];
            float b1 = Bs[kk][tx * 2 + 1];
            acc[0][0] = fmaf(a0, b0, acc[0][0]);
            acc[0][1] = fmaf(a0, b1, acc[0][1]);
            acc[1][0] = fmaf(a1, b0, acc[1][0]);
            acc[1][1] = fmaf(a1, b1, acc[1][1]);
        }
        __syncthreads();
    }
    #pragma unroll
    for (int i = 0; i < 2; i++) {
        int m = bm + ty * 2 + i;
        #pragma unroll
        for (int j = 0; j < 2; j++) {
            int nn = bn + tx * 2 + j;
            C[(size_t)m * N + nn] = silu(acc[i][j] + bias[nn]);
        }
    }
}

// ============================================================================
// final reduction: 8 blocks x 256 threads (one atom each) -> g_part; then sum
// ============================================================================
__global__ __launch_bounds__(256) void final1_kernel(
    const float* __restrict__ h2, const float* __restrict__ Wa3,
    const float* __restrict__ ba3)
{
    __shared__ float w[H2D];
    __shared__ double red[256];
    int t = threadIdx.x;
    if (t < H2D) w[t] = Wa3[t];
    __syncthreads();
    int a = blockIdx.x * 256 + t;
    const float* hp = h2 + (size_t)a * H2D;
    float acc = 0.f;
    #pragma unroll 4
    for (int j = 0; j < H2D; j++) acc = fmaf(hp[j], w[j], acc);
    red[t] = (double)(acc + ba3[0]);
    __syncthreads();
    for (int off = 128; off > 0; off >>= 1) {
        if (t < off) red[t] += red[t + off];
        __syncthreads();
    }
    if (t == 0) g_part[blockIdx.x] = red[0];
}

__global__ void final2_kernel(float* __restrict__ out)
{
    if (threadIdx.x == 0) {
        double s = 0.0;
        #pragma unroll
        for (int i = 0; i < 8; i++) s += g_part[i];
        out[0] = (float)s;
    }
}

// ============================================================================
extern "C" void kernel_launch(void* const* d_in, const int* in_sizes, int n_in,
                              void* d_out, int out_size)
{
    const float* rij = (const float*)d_in[0];
    const float* Wr1 = (const float*)d_in[1];
    const float* br1 = (const float*)d_in[2];
    const float* Wr2 = (const float*)d_in[3];
    const float* br2 = (const float*)d_in[4];
    const float* Ws1 = (const float*)d_in[5];
    const float* bs1 = (const float*)d_in[6];
    const float* Ws2 = (const float*)d_in[7];
    const float* bs2 = (const float*)d_in[8];
    const float* Wa1 = (const float*)d_in[9];
    const float* ba1 = (const float*)d_in[10];
    const float* Wa2 = (const float*)d_in[11];
    const float* ba2 = (const float*)d_in[12];
    const float* Wa3 = (const float*)d_in[13];
    const float* ba3 = (const float*)d_in[14];
    const int*   fa  = (const int*)d_in[15];
    const int*   sp  = (const int*)d_in[16];
    float* out = (float*)d_out;

    float *ph1, *ph2;
    cudaGetSymbolAddress((void**)&ph1, g_h1);
    cudaGetSymbolAddress((void**)&ph2, g_h2);

    // opt-in to >48KB dynamic smem (idempotent; not an allocation)
    cudaFuncSetAttribute(fused_kernel,
                         cudaFuncAttributeMaxDynamicSharedMemorySize,
                         FUSED_SMEM_BYTES);

    seg_kernel<<<NEDGE / 256, 256>>>(fa);
    fused_kernel<<<NATOMS, 256, FUSED_SMEM_BYTES>>>(rij, Wr1, br1, Wr2, br2);
    embsort_kernel<<<1, 256>>>(Ws1, bs1, Ws2, bs2, sp);
    weff_kernel<<<dim3(NFEAT, 4), 256>>>(Wa1);
    gemm1_kernel<<<dim3(MAXCHUNK, 2), 256>>>(ba1);
    gemm2_kernel<<<dim3(H2D / 32, NATOMS / 32), 256>>>(ph1, Wa2, ba2, ph2);
    final1_kernel<<<8, 256>>>(ph2, Wa3, ba3);
    final2_kernel<<<1, 32>>>(out);
}